// round 13
// baseline (speedup 1.0000x reference)
#include <cuda_runtime.h>
#include <cuda_fp16.h>
#include <cstdint>

#define N_MAX   100000
#define E_MAX   3200000
#define FIN     128
#define HID     64
#define OUTD    32
#define SCAN_B  ((N_MAX + 1023) / 1024)   // 98

__device__ __align__(16) __half g_hh [(size_t)N_MAX * HID];   // fp16 scaled hs / u
__device__ __align__(16) __half g_vv [(size_t)N_MAX * HID];   // fp16 v
__device__ __align__(16) __half g_ag [(size_t)N_MAX * HID];   // fp16 inter-layer agg
__device__ int   g_cnt   [N_MAX];
__device__ float g_dinv  [N_MAX];
__device__ int   g_rowptr[N_MAX + 1];
__device__ int   g_cursor[N_MAX];
__device__ int   g_bsum  [SCAN_B];
__device__ int   g_boff  [SCAN_B];
__device__ int   g_csr   [E_MAX];
__device__ int   g_is64;

// k_gemm output modes
#define OM_H16S    0   // fp16 scaled by dinv[node] -> g_hh
#define OM_SPLIT16 1   // fp16: cols 0-63 -> g_hh (u), 64-127 -> g_vv (v)

__device__ __forceinline__ unsigned long long fma2(unsigned long long a,
                                                   unsigned long long b,
                                                   unsigned long long c) {
    unsigned long long d;
    asm("fma.rn.f32x2 %0, %1, %2, %3;" : "=l"(d) : "l"(a), "l"(b), "l"(c));
    return d;
}
__device__ __forceinline__ unsigned long long pack2(float lo, float hi) {
    unsigned long long r;
    asm("mov.b64 %0, {%1, %2};" : "=l"(r) : "f"(lo), "f"(hi));
    return r;
}
__device__ __forceinline__ float2 unpack2(unsigned long long v) {
    float2 r;
    asm("mov.b64 {%0, %1}, %2;" : "=f"(r.x), "=f"(r.y) : "l"(v));
    return r;
}
__device__ __forceinline__ void h16x8_to_f32(uint4 r, float* v) {
    const __half2* h = (const __half2*)&r;
    float2 f0 = __half22float2(h[0]);
    float2 f1 = __half22float2(h[1]);
    float2 f2 = __half22float2(h[2]);
    float2 f3 = __half22float2(h[3]);
    v[0] = f0.x; v[1] = f0.y; v[2] = f1.x; v[3] = f1.y;
    v[4] = f2.x; v[5] = f2.y; v[6] = f3.x; v[7] = f3.y;
}

__device__ __forceinline__ int load_idx(const void* buf, size_t e, int is64, int n) {
    int v;
    if (is64) v = (int)((const long long*)buf)[e];
    else      v = ((const int*)buf)[e];
    if ((unsigned)v >= (unsigned)n) v = 0;
    return v;
}

// ---- detect dtype (block 0) + zero cnt (all blocks) ----
__global__ void k_detect_zero(const int* __restrict__ raw, int n) {
    int i = blockIdx.x * blockDim.x + threadIdx.x;
    if (i < n) g_cnt[i] = 0;
    if (blockIdx.x == 0) {
        __shared__ int s_nz;
        if (threadIdx.x == 0) s_nz = 0;
        __syncthreads();
        int nz = 0;
        for (int k = threadIdx.x; k < 512; k += blockDim.x)
            nz |= raw[2 * k + 1];
        if (nz) atomicOr(&s_nz, 1);
        __syncthreads();
        if (threadIdx.x == 0) g_is64 = (s_nz == 0) ? 1 : 0;
    }
}

__global__ void k_count(const void* __restrict__ ei, int nE, int n) {
    int e = blockIdx.x * blockDim.x + threadIdx.x;
    if (e >= nE) return;
    int is64 = g_is64;
    int c = load_idx(ei, (size_t)nE + e, is64, n);
    atomicAdd(&g_cnt[c], 1);
}

__global__ void k_scan1(int n) {
    __shared__ int sh[1024];
    int tid = threadIdx.x;
    int i = blockIdx.x * 1024 + tid;
    int v = (i < n) ? g_cnt[i] : 0;
    if (i < n) g_dinv[i] = rsqrtf((float)v + 1.0f);
    sh[tid] = v;
    __syncthreads();
    #pragma unroll
    for (int off = 1; off < 1024; off <<= 1) {
        int t = (tid >= off) ? sh[tid - off] : 0;
        __syncthreads();
        sh[tid] += t;
        __syncthreads();
    }
    if (i < n) g_rowptr[i] = sh[tid] - v;
    if (tid == 1023) g_bsum[blockIdx.x] = sh[1023];
}

__global__ void k_scan2(int n) {
    __shared__ int sh[128];
    int tid = threadIdx.x;
    int v = (tid < SCAN_B) ? g_bsum[tid] : 0;
    sh[tid] = v;
    __syncthreads();
    #pragma unroll
    for (int off = 1; off < 128; off <<= 1) {
        int t = (tid >= off) ? sh[tid - off] : 0;
        __syncthreads();
        sh[tid] += t;
        __syncthreads();
    }
    if (tid < SCAN_B) g_boff[tid] = sh[tid] - v;
    if (tid == 127) g_rowptr[n] = sh[127];
}

__global__ void k_scan3(int n) {
    int i = blockIdx.x * blockDim.x + threadIdx.x;
    if (i >= n) return;
    int r = g_rowptr[i] + g_boff[i >> 10];
    g_rowptr[i] = r;
    g_cursor[i] = r;
}

__global__ void k_fill(const void* __restrict__ ei, int nE, int n) {
    int e = blockIdx.x * blockDim.x + threadIdx.x;
    if (e >= nE) return;
    int is64 = g_is64;
    int r = load_idx(ei, (size_t)e, is64, n);
    int c = load_idx(ei, (size_t)nE + e, is64, n);
    int pos = atomicAdd(&g_cursor[c], 1);
    if (pos >= 0 && pos < E_MAX) g_csr[pos] = r;
}

// ---------------- register-tiled GEMM (f32x2) ----------------
template<int K, int M, bool RELU, bool SRC_AGG16, int OMODE>
__global__ void k_gemm(const float* __restrict__ Xext,
                       const float* __restrict__ Bk,
                       const float* __restrict__ W, int n) {
    constexpr int KC = (K < 64) ? K : 64;
    constexpr int JG = M / 8;
    constexpr int THREADS = 16 * JG;
    constexpr int XS = 132;
    __shared__ float sW[KC * M];
    __shared__ float sXT[KC][XS];

    int tid = threadIdx.x;
    int jg  = tid & (JG - 1);
    int ng  = tid / JG;
    int n0  = blockIdx.x * 128;

    unsigned long long acc2[8][4];
    #pragma unroll
    for (int e = 0; e < 8; e++)
        #pragma unroll
        for (int jj = 0; jj < 4; jj++) acc2[e][jj] = 0ull;

    for (int kc = 0; kc < K; kc += KC) {
        if (OMODE == OM_SPLIT16) {
            for (int i = tid; i < KC * M; i += THREADS) {
                int k = i / M, j = i % M;
                sW[i] = (j < 64) ? W[(size_t)(kc + k) * 64 + j]
                                 : W[(size_t)(kc + k + K) * 64 + (j - 64)];
            }
        } else {
            for (int i = tid; i < KC * M; i += THREADS)
                sW[i] = W[(size_t)kc * M + i];
        }
        for (int nl = tid; nl < 128; nl += THREADS) {
            int node = n0 + nl;
            if (SRC_AGG16) {
                #pragma unroll
                for (int q = 0; q < KC / 8; q++) {
                    float v[8] = {0,0,0,0,0,0,0,0};
                    if (node < n) {
                        uint4 r = *(const uint4*)(g_ag + (size_t)node * K + kc + q * 8);
                        h16x8_to_f32(r, v);
                        if (RELU) {
                            #pragma unroll
                            for (int i = 0; i < 8; i++)
                                v[i] = fmaxf(v[i] + Bk[kc + q * 8 + i], 0.f);
                        }
                    }
                    #pragma unroll
                    for (int i = 0; i < 8; i++) sXT[q * 8 + i][nl] = v[i];
                }
            } else {
                #pragma unroll
                for (int q = 0; q < KC / 4; q++) {
                    float4 v = make_float4(0.f, 0.f, 0.f, 0.f);
                    if (node < n) {
                        v = *(const float4*)(Xext + (size_t)node * K + kc + q * 4);
                        if (RELU) {
                            v.x = fmaxf(v.x + Bk[kc + q * 4 + 0], 0.f);
                            v.y = fmaxf(v.y + Bk[kc + q * 4 + 1], 0.f);
                            v.z = fmaxf(v.z + Bk[kc + q * 4 + 2], 0.f);
                            v.w = fmaxf(v.w + Bk[kc + q * 4 + 3], 0.f);
                        }
                    }
                    sXT[q * 4 + 0][nl] = v.x;
                    sXT[q * 4 + 1][nl] = v.y;
                    sXT[q * 4 + 2][nl] = v.z;
                    sXT[q * 4 + 3][nl] = v.w;
                }
            }
        }
        __syncthreads();

        #pragma unroll 4
        for (int k = 0; k < KC; k++) {
            float4 a0 = *(const float4*)&sXT[k][ng * 8];
            float4 a1 = *(const float4*)&sXT[k][ng * 8 + 4];
            const float2* wr = (const float2*)&sW[k * M + jg * 8];
            unsigned long long w0 = pack2(wr[0].x, wr[0].y);
            unsigned long long w1 = pack2(wr[1].x, wr[1].y);
            unsigned long long w2 = pack2(wr[2].x, wr[2].y);
            unsigned long long w3 = pack2(wr[3].x, wr[3].y);
            float av[8] = {a0.x, a0.y, a0.z, a0.w, a1.x, a1.y, a1.z, a1.w};
            #pragma unroll
            for (int e = 0; e < 8; e++) {
                unsigned long long x2 = pack2(av[e], av[e]);
                acc2[e][0] = fma2(x2, w0, acc2[e][0]);
                acc2[e][1] = fma2(x2, w1, acc2[e][1]);
                acc2[e][2] = fma2(x2, w2, acc2[e][2]);
                acc2[e][3] = fma2(x2, w3, acc2[e][3]);
            }
        }
        __syncthreads();
    }

    #pragma unroll
    for (int e = 0; e < 8; e++) {
        int node = n0 + ng * 8 + e;
        if (node >= n) continue;
        uint4 pkt;
        __half2* ph = (__half2*)&pkt;
        if (OMODE == OM_H16S) {
            float dv = g_dinv[node];
            #pragma unroll
            for (int jj = 0; jj < 4; jj++) {
                float2 f = unpack2(acc2[e][jj]);
                ph[jj] = __floats2half2_rn(f.x * dv, f.y * dv);
            }
            *(uint4*)(g_hh + (size_t)node * M + jg * 8) = pkt;
        } else {
            #pragma unroll
            for (int jj = 0; jj < 4; jj++) {
                float2 f = unpack2(acc2[e][jj]);
                ph[jj] = __floats2half2_rn(f.x, f.y);
            }
            __half* dst = (jg < 8) ? (g_hh + (size_t)node * 64 + jg * 8)
                                   : (g_vv + (size_t)node * 64 + (jg - 8) * 8);
            *(uint4*)dst = pkt;
        }
    }
}

// ---------------- aggregation: one node per warp, edge-parallel ----------------
// 32 lanes = EPW edge-slices x LPS lanes; warp strides its CSR row by 2*EPW.
// acc = hs[node] + sum_e hs[src(e)]; out = dinv[node]*acc (+bias fp32 when FINAL).
template<int H, bool FINAL>
__global__ void k_aggw(int n, const float* __restrict__ bias,
                       float* __restrict__ zout) {
    constexpr int LPS = H / 8;       // lanes per slice: 8 (H=64), 4 (H=32)
    constexpr int EPW = 32 / LPS;    // edge slices per warp: 4 or 8
    int node = (blockIdx.x * blockDim.x + threadIdx.x) >> 5;
    int lane = threadIdx.x & 31;
    int grp  = lane / LPS;
    int fl   = lane % LPS;
    if (node >= n) return;

    float acc[8] = {0,0,0,0,0,0,0,0};
    float v0[8], v1[8];

    // self term counted once (group 0)
    if (grp == 0) {
        uint4 rs = *(const uint4*)(g_hh + (size_t)node * H + fl * 8);
        h16x8_to_f32(rs, acc);
    }

    int beg = g_rowptr[node];
    int end = g_rowptr[node + 1];
    int e = beg + grp;
    // 2x unrolled edge-parallel loop (2*EPW edges per warp iteration)
    for (; e + EPW < end; e += 2 * EPW) {
        int s0 = g_csr[e];
        int s1 = g_csr[e + EPW];
        uint4 r0 = *(const uint4*)(g_hh + (size_t)s0 * H + fl * 8);
        uint4 r1 = *(const uint4*)(g_hh + (size_t)s1 * H + fl * 8);
        h16x8_to_f32(r0, v0);
        h16x8_to_f32(r1, v1);
        #pragma unroll
        for (int i = 0; i < 8; i++) acc[i] += v0[i];
        #pragma unroll
        for (int i = 0; i < 8; i++) acc[i] += v1[i];
    }
    if (e < end) {
        int s0 = g_csr[e];
        uint4 r0 = *(const uint4*)(g_hh + (size_t)s0 * H + fl * 8);
        h16x8_to_f32(r0, v0);
        #pragma unroll
        for (int i = 0; i < 8; i++) acc[i] += v0[i];
    }

    // reduce across edge groups (lanes with equal fl)
    #pragma unroll
    for (int off = 16; off >= LPS; off >>= 1) {
        #pragma unroll
        for (int i = 0; i < 8; i++)
            acc[i] += __shfl_down_sync(0xffffffffu, acc[i], off);
    }

    if (grp == 0) {
        float dv = g_dinv[node];
        if (FINAL) {
            float* dst = zout + (size_t)node * H + fl * 8;
            float4 b0 = *(const float4*)(bias + fl * 8);
            float4 b1 = *(const float4*)(bias + fl * 8 + 4);
            *(float4*)(dst)     = make_float4(acc[0] * dv + b0.x, acc[1] * dv + b0.y,
                                              acc[2] * dv + b0.z, acc[3] * dv + b0.w);
            *(float4*)(dst + 4) = make_float4(acc[4] * dv + b1.x, acc[5] * dv + b1.y,
                                              acc[6] * dv + b1.z, acc[7] * dv + b1.w);
        } else {
            uint4 pkt;
            __half2* ph = (__half2*)&pkt;
            #pragma unroll
            for (int jj = 0; jj < 4; jj++)
                ph[jj] = __floats2half2_rn(acc[jj * 2] * dv, acc[jj * 2 + 1] * dv);
            *(uint4*)(g_ag + (size_t)node * H + fl * 8) = pkt;
        }
    }
}

// ---------------- decoder-lite (fp16 u/v) ----------------
__global__ void k_decode_lite(const void* __restrict__ eli,
                              const float* __restrict__ b1,
                              const float* __restrict__ w2,
                              const float* __restrict__ b2,
                              float* __restrict__ out, int nE, int nNodes) {
    int gw   = (blockIdx.x * blockDim.x + threadIdx.x) >> 5;
    int lane = threadIdx.x & 31;
    int sub  = lane >> 3;
    int fl   = lane & 7;

    int e = gw * 4 + sub;
    if (e >= nE) return;

    int is64 = g_is64;
    int src = load_idx(eli, (size_t)e, is64, nNodes);
    int dst = load_idx(eli, (size_t)nE + e, is64, nNodes);

    uint4 ru = *(const uint4*)(g_hh + (size_t)src * HID + fl * 8);
    uint4 rv = *(const uint4*)(g_vv + (size_t)dst * HID + fl * 8);
    float uu[8], vv[8];
    h16x8_to_f32(ru, uu);
    h16x8_to_f32(rv, vv);
    float4 b0 = *(const float4*)(b1 + fl * 8);
    float4 b1v = *(const float4*)(b1 + fl * 8 + 4);
    float4 w0 = *(const float4*)(w2 + fl * 8);
    float4 w1 = *(const float4*)(w2 + fl * 8 + 4);
    float bb[8] = {b0.x, b0.y, b0.z, b0.w, b1v.x, b1v.y, b1v.z, b1v.w};
    float ww[8] = {w0.x, w0.y, w0.z, w0.w, w1.x, w1.y, w1.z, w1.w};

    float p = 0.f;
    #pragma unroll
    for (int i = 0; i < 8; i++)
        p += fmaxf(uu[i] + vv[i] + bb[i], 0.f) * ww[i];

    p += __shfl_down_sync(0xffffffffu, p, 4, 8);
    p += __shfl_down_sync(0xffffffffu, p, 2, 8);
    p += __shfl_down_sync(0xffffffffu, p, 1, 8);

    if (fl == 0) out[e] = p + b2[0];
}

extern "C" void kernel_launch(void* const* d_in, const int* in_sizes, int n_in,
                              void* d_out, int out_size) {
    const float* x    = (const float*)d_in[0];
    const void*  ei   = d_in[1];
    const void*  eli  = d_in[2];
    const float* W1   = (const float*)d_in[3];
    const float* b1   = (const float*)d_in[4];
    const float* W2   = (const float*)d_in[5];
    const float* b2   = (const float*)d_in[6];
    const float* W3   = (const float*)d_in[7];
    const float* b3   = (const float*)d_in[8];
    const float* lpW1 = (const float*)d_in[9];
    const float* lpb1 = (const float*)d_in[10];
    const float* lpW2 = (const float*)d_in[11];
    const float* lpb2 = (const float*)d_in[12];
    float* out = (float*)d_out;

    int N  = in_sizes[0] / FIN;
    int E  = in_sizes[1] / 2;
    int EL = in_sizes[2] / 2;

    const int T = 256;
    int nBlkN = (N + T - 1) / T;
    int nBlkE = (E + T - 1) / T;
    int scanBlocks = (N + 1023) / 1024;
    int gemmBlocks = (N + 127) / 128;

    // one node per warp: 8 warps per 256-thread block
    int aggBlocks = (N + 7) / 8;

    float* zout = out + EL;

    // CSR build
    k_detect_zero<<<nBlkN, T>>>((const int*)ei, N);
    k_count<<<nBlkE, T>>>(ei, E, N);
    k_scan1<<<scanBlocks, 1024>>>(N);
    k_scan2<<<1, 128>>>(N);
    k_scan3<<<nBlkN, T>>>(N);
    k_fill<<<nBlkE, T>>>(ei, E, N);

    // encoder
    k_gemm<FIN, HID, false, false, OM_H16S><<<gemmBlocks, 128>>>(x, nullptr, W1, N);
    k_aggw<HID, false><<<aggBlocks, T>>>(N, nullptr, nullptr);

    k_gemm<HID, HID, true, true, OM_H16S><<<gemmBlocks, 128>>>(nullptr, b1, W2, N);
    k_aggw<HID, false><<<aggBlocks, T>>>(N, nullptr, nullptr);

    k_gemm<HID, OUTD, true, true, OM_H16S><<<gemmBlocks, 64>>>(nullptr, b2, W3, N);
    k_aggw<OUTD, true><<<aggBlocks, T>>>(N, b3, zout);

    // fused decoder precompute: [u|v] = z @ [lpW1_top | lpW1_bot]
    k_gemm<OUTD, 128, false, false, OM_SPLIT16><<<gemmBlocks, 256>>>(zout, nullptr, lpW1, N);

    // decoder
    int warpsD = (EL + 3) / 4;
    int decBlocks = (warpsD * 32 + T - 1) / T;
    k_decode_lite<<<decBlocks, T>>>(eli, lpb1, lpW2, lpb2, out, EL, N);
}

// round 14
// speedup vs baseline: 1.0357x; 1.0357x over previous
#include <cuda_runtime.h>
#include <cuda_fp16.h>
#include <cstdint>

#define N_MAX   100000
#define E_MAX   3200000
#define FIN     128
#define HID     64
#define OUTD    32
#define SCAN_B  ((N_MAX + 1023) / 1024)   // 98

__device__ __align__(16) float  g_agg[(size_t)N_MAX * HID];   // fp32 aggregate
__device__ __align__(16) __half g_hh [(size_t)N_MAX * HID];   // fp16 scaled hs / u
__device__ __align__(16) __half g_vv [(size_t)N_MAX * HID];   // fp16 v
__device__ int   g_cnt   [N_MAX];
__device__ float g_dinv  [N_MAX];
__device__ int   g_rowptr[N_MAX + 1];
__device__ int   g_cursor[N_MAX];
__device__ int   g_bsum  [SCAN_B];
__device__ int   g_boff  [SCAN_B];
__device__ int   g_csr   [E_MAX];                             // src only
__device__ int   g_is64;

// k_gemm output modes
#define OM_H16S    0   // fp16, scaled by dinv[node], -> g_hh
#define OM_SPLIT16 1   // fp16 u -> g_hh, v -> g_vv (M=128, W = [lpW1_top|lpW1_bot])

__device__ __forceinline__ unsigned long long fma2(unsigned long long a,
                                                   unsigned long long b,
                                                   unsigned long long c) {
    unsigned long long d;
    asm("fma.rn.f32x2 %0, %1, %2, %3;" : "=l"(d) : "l"(a), "l"(b), "l"(c));
    return d;
}
__device__ __forceinline__ unsigned long long pack2(float lo, float hi) {
    unsigned long long r;
    asm("mov.b64 %0, {%1, %2};" : "=l"(r) : "f"(lo), "f"(hi));
    return r;
}
__device__ __forceinline__ float2 unpack2(unsigned long long v) {
    float2 r;
    asm("mov.b64 {%0, %1}, %2;" : "=f"(r.x), "=f"(r.y) : "l"(v));
    return r;
}
__device__ __forceinline__ void h16x8_to_f32(uint4 r, float* v) {
    const __half2* h = (const __half2*)&r;
    float2 f0 = __half22float2(h[0]);
    float2 f1 = __half22float2(h[1]);
    float2 f2 = __half22float2(h[2]);
    float2 f3 = __half22float2(h[3]);
    v[0] = f0.x; v[1] = f0.y; v[2] = f1.x; v[3] = f1.y;
    v[4] = f2.x; v[5] = f2.y; v[6] = f3.x; v[7] = f3.y;
}

__global__ void k_detect(const int* __restrict__ raw) {
    __shared__ int s_nz;
    if (threadIdx.x == 0) s_nz = 0;
    __syncthreads();
    int nz = 0;
    for (int i = threadIdx.x; i < 512; i += blockDim.x)
        nz |= raw[2 * i + 1];
    if (nz) atomicOr(&s_nz, 1);
    __syncthreads();
    if (threadIdx.x == 0) g_is64 = (s_nz == 0) ? 1 : 0;
}

__device__ __forceinline__ int load_idx(const void* buf, size_t e, int is64, int n) {
    int v;
    if (is64) v = (int)((const long long*)buf)[e];
    else      v = ((const int*)buf)[e];
    if ((unsigned)v >= (unsigned)n) v = 0;
    return v;
}

__global__ void k_zero_cnt(int n) {
    int i = blockIdx.x * blockDim.x + threadIdx.x;
    if (i < n) g_cnt[i] = 0;
}

__global__ void k_count(const void* __restrict__ ei, int nE, int n) {
    int e = blockIdx.x * blockDim.x + threadIdx.x;
    if (e >= nE) return;
    int is64 = g_is64;
    int c = load_idx(ei, (size_t)nE + e, is64, n);
    atomicAdd(&g_cnt[c], 1);
}

__global__ void k_scan1(int n) {
    __shared__ int sh[1024];
    int tid = threadIdx.x;
    int i = blockIdx.x * 1024 + tid;
    int v = (i < n) ? g_cnt[i] : 0;
    if (i < n) g_dinv[i] = rsqrtf((float)v + 1.0f);
    sh[tid] = v;
    __syncthreads();
    #pragma unroll
    for (int off = 1; off < 1024; off <<= 1) {
        int t = (tid >= off) ? sh[tid - off] : 0;
        __syncthreads();
        sh[tid] += t;
        __syncthreads();
    }
    if (i < n) g_rowptr[i] = sh[tid] - v;
    if (tid == 1023) g_bsum[blockIdx.x] = sh[1023];
}

__global__ void k_scan2(int n) {
    __shared__ int sh[128];
    int tid = threadIdx.x;
    int v = (tid < SCAN_B) ? g_bsum[tid] : 0;
    sh[tid] = v;
    __syncthreads();
    #pragma unroll
    for (int off = 1; off < 128; off <<= 1) {
        int t = (tid >= off) ? sh[tid - off] : 0;
        __syncthreads();
        sh[tid] += t;
        __syncthreads();
    }
    if (tid < SCAN_B) g_boff[tid] = sh[tid] - v;
    if (tid == 127) g_rowptr[n] = sh[127];
}

__global__ void k_scan3(int n) {
    int i = blockIdx.x * blockDim.x + threadIdx.x;
    if (i >= n) return;
    int r = g_rowptr[i] + g_boff[i >> 10];
    g_rowptr[i] = r;
    g_cursor[i] = r;
}

__global__ void k_fill(const void* __restrict__ ei, int nE, int n) {
    int e = blockIdx.x * blockDim.x + threadIdx.x;
    if (e >= nE) return;
    int is64 = g_is64;
    int r = load_idx(ei, (size_t)e, is64, n);
    int c = load_idx(ei, (size_t)nE + e, is64, n);
    int pos = atomicAdd(&g_cursor[c], 1);
    if (pos >= 0 && pos < E_MAX) g_csr[pos] = r;
}

// ---------------- register-tiled GEMM (f32x2) ----------------
template<int K, int M, bool RELU, bool SRC_AGG, int OMODE>
__global__ void k_gemm(const float* __restrict__ Xext,
                       const float* __restrict__ Bk,
                       const float* __restrict__ W, int n) {
    constexpr int KC = (K < 64) ? K : 64;
    constexpr int JG = M / 8;
    constexpr int THREADS = 16 * JG;
    constexpr int XS = 132;
    __shared__ float sW[KC * M];
    __shared__ float sXT[KC][XS];

    int tid = threadIdx.x;
    int jg  = tid & (JG - 1);
    int ng  = tid / JG;
    int n0  = blockIdx.x * 128;

    unsigned long long acc2[8][4];
    #pragma unroll
    for (int e = 0; e < 8; e++)
        #pragma unroll
        for (int jj = 0; jj < 4; jj++) acc2[e][jj] = 0ull;

    const float* src = SRC_AGG ? (const float*)g_agg : Xext;

    for (int kc = 0; kc < K; kc += KC) {
        if (OMODE == OM_SPLIT16) {
            for (int i = tid; i < KC * M; i += THREADS) {
                int k = i / M, j = i % M;
                sW[i] = (j < 64) ? W[(size_t)(kc + k) * 64 + j]
                                 : W[(size_t)(kc + k + K) * 64 + (j - 64)];
            }
        } else {
            for (int i = tid; i < KC * M; i += THREADS)
                sW[i] = W[(size_t)kc * M + i];
        }
        for (int nl = tid; nl < 128; nl += THREADS) {
            int node = n0 + nl;
            #pragma unroll
            for (int q = 0; q < KC / 4; q++) {
                float4 v = make_float4(0.f, 0.f, 0.f, 0.f);
                if (node < n) {
                    v = *(const float4*)(src + (size_t)node * K + kc + q * 4);
                    if (RELU) {
                        v.x = fmaxf(v.x + Bk[kc + q * 4 + 0], 0.f);
                        v.y = fmaxf(v.y + Bk[kc + q * 4 + 1], 0.f);
                        v.z = fmaxf(v.z + Bk[kc + q * 4 + 2], 0.f);
                        v.w = fmaxf(v.w + Bk[kc + q * 4 + 3], 0.f);
                    }
                }
                sXT[q * 4 + 0][nl] = v.x;
                sXT[q * 4 + 1][nl] = v.y;
                sXT[q * 4 + 2][nl] = v.z;
                sXT[q * 4 + 3][nl] = v.w;
            }
        }
        __syncthreads();

        #pragma unroll 4
        for (int k = 0; k < KC; k++) {
            float4 a0 = *(const float4*)&sXT[k][ng * 8];
            float4 a1 = *(const float4*)&sXT[k][ng * 8 + 4];
            const float2* wr = (const float2*)&sW[k * M + jg * 8];
            unsigned long long w0 = pack2(wr[0].x, wr[0].y);
            unsigned long long w1 = pack2(wr[1].x, wr[1].y);
            unsigned long long w2 = pack2(wr[2].x, wr[2].y);
            unsigned long long w3 = pack2(wr[3].x, wr[3].y);
            float av[8] = {a0.x, a0.y, a0.z, a0.w, a1.x, a1.y, a1.z, a1.w};
            #pragma unroll
            for (int e = 0; e < 8; e++) {
                unsigned long long x2 = pack2(av[e], av[e]);
                acc2[e][0] = fma2(x2, w0, acc2[e][0]);
                acc2[e][1] = fma2(x2, w1, acc2[e][1]);
                acc2[e][2] = fma2(x2, w2, acc2[e][2]);
                acc2[e][3] = fma2(x2, w3, acc2[e][3]);
            }
        }
        __syncthreads();
    }

    #pragma unroll
    for (int e = 0; e < 8; e++) {
        int node = n0 + ng * 8 + e;
        if (node >= n) continue;
        uint4 pkt;
        __half2* ph = (__half2*)&pkt;
        if (OMODE == OM_H16S) {
            float dv = g_dinv[node];
            #pragma unroll
            for (int jj = 0; jj < 4; jj++) {
                float2 f = unpack2(acc2[e][jj]);
                ph[jj] = __floats2half2_rn(f.x * dv, f.y * dv);
            }
            *(uint4*)(g_hh + (size_t)node * M + jg * 8) = pkt;
        } else {   // OM_SPLIT16
            #pragma unroll
            for (int jj = 0; jj < 4; jj++) {
                float2 f = unpack2(acc2[e][jj]);
                ph[jj] = __floats2half2_rn(f.x, f.y);
            }
            __half* dst = (jg < 8) ? (g_hh + (size_t)node * 64 + jg * 8)
                                   : (g_vv + (size_t)node * 64 + (jg - 8) * 8);
            *(uint4*)dst = pkt;
        }
    }
}

// ---------------- aggregation over scaled fp16 hs ----------------
// acc = hs[c] + sum_e hs[src(e)];  result = dinv[c] * acc  (+bias when FINAL)
// FINAL writes zout fp32; else writes g_agg fp32.
template<int H, bool FINAL>
__global__ void k_agg16(int n, const float* __restrict__ bias,
                        float* __restrict__ zout) {
    constexpr int LPN = H / 8;
    constexpr int NPW = 32 / LPN;
    int gw   = (blockIdx.x * blockDim.x + threadIdx.x) >> 5;
    int lane = threadIdx.x & 31;
    int node = gw * NPW + lane / LPN;
    int fl   = lane % LPN;
    if (node >= n) return;

    float acc[8], v0[8], v1[8];
    uint4 rs = *(const uint4*)(g_hh + (size_t)node * H + fl * 8);
    h16x8_to_f32(rs, acc);

    int beg = g_rowptr[node];
    int end = g_rowptr[node + 1];
    int e = beg;
    for (; e + 1 < end; e += 2) {
        int s0 = g_csr[e];
        int s1 = g_csr[e + 1];
        uint4 r0 = *(const uint4*)(g_hh + (size_t)s0 * H + fl * 8);
        uint4 r1 = *(const uint4*)(g_hh + (size_t)s1 * H + fl * 8);
        h16x8_to_f32(r0, v0);
        h16x8_to_f32(r1, v1);
        #pragma unroll
        for (int i = 0; i < 8; i++) acc[i] += v0[i];
        #pragma unroll
        for (int i = 0; i < 8; i++) acc[i] += v1[i];
    }
    if (e < end) {
        int s0 = g_csr[e];
        uint4 r0 = *(const uint4*)(g_hh + (size_t)s0 * H + fl * 8);
        h16x8_to_f32(r0, v0);
        #pragma unroll
        for (int i = 0; i < 8; i++) acc[i] += v0[i];
    }

    float dv = g_dinv[node];
    if (FINAL) {
        float* dst = zout + (size_t)node * H + fl * 8;
        float4 b0 = *(const float4*)(bias + fl * 8);
        float4 b1 = *(const float4*)(bias + fl * 8 + 4);
        *(float4*)(dst)     = make_float4(acc[0] * dv + b0.x, acc[1] * dv + b0.y,
                                          acc[2] * dv + b0.z, acc[3] * dv + b0.w);
        *(float4*)(dst + 4) = make_float4(acc[4] * dv + b1.x, acc[5] * dv + b1.y,
                                          acc[6] * dv + b1.z, acc[7] * dv + b1.w);
    } else {
        float* dst = g_agg + (size_t)node * H + fl * 8;
        *(float4*)(dst)     = make_float4(acc[0] * dv, acc[1] * dv, acc[2] * dv, acc[3] * dv);
        *(float4*)(dst + 4) = make_float4(acc[4] * dv, acc[5] * dv, acc[6] * dv, acc[7] * dv);
    }
}

// ---------------- decoder-lite (fp16 u/v) ----------------
__global__ void k_decode_lite(const void* __restrict__ eli,
                              const float* __restrict__ b1,
                              const float* __restrict__ w2,
                              const float* __restrict__ b2,
                              float* __restrict__ out, int nE, int nNodes) {
    int gw   = (blockIdx.x * blockDim.x + threadIdx.x) >> 5;
    int lane = threadIdx.x & 31;
    int sub  = lane >> 3;
    int fl   = lane & 7;

    int e = gw * 4 + sub;
    if (e >= nE) return;

    int is64 = g_is64;
    int src = load_idx(eli, (size_t)e, is64, nNodes);
    int dst = load_idx(eli, (size_t)nE + e, is64, nNodes);

    uint4 ru = *(const uint4*)(g_hh + (size_t)src * HID + fl * 8);
    uint4 rv = *(const uint4*)(g_vv + (size_t)dst * HID + fl * 8);
    float uu[8], vv[8];
    h16x8_to_f32(ru, uu);
    h16x8_to_f32(rv, vv);
    float4 b0 = *(const float4*)(b1 + fl * 8);
    float4 b1v = *(const float4*)(b1 + fl * 8 + 4);
    float4 w0 = *(const float4*)(w2 + fl * 8);
    float4 w1 = *(const float4*)(w2 + fl * 8 + 4);
    float bb[8] = {b0.x, b0.y, b0.z, b0.w, b1v.x, b1v.y, b1v.z, b1v.w};
    float ww[8] = {w0.x, w0.y, w0.z, w0.w, w1.x, w1.y, w1.z, w1.w};

    float p = 0.f;
    #pragma unroll
    for (int i = 0; i < 8; i++)
        p += fmaxf(uu[i] + vv[i] + bb[i], 0.f) * ww[i];

    p += __shfl_down_sync(0xffffffffu, p, 4, 8);
    p += __shfl_down_sync(0xffffffffu, p, 2, 8);
    p += __shfl_down_sync(0xffffffffu, p, 1, 8);

    if (fl == 0) out[e] = p + b2[0];
}

extern "C" void kernel_launch(void* const* d_in, const int* in_sizes, int n_in,
                              void* d_out, int out_size) {
    const float* x    = (const float*)d_in[0];
    const void*  ei   = d_in[1];
    const void*  eli  = d_in[2];
    const float* W1   = (const float*)d_in[3];
    const float* b1   = (const float*)d_in[4];
    const float* W2   = (const float*)d_in[5];
    const float* b2   = (const float*)d_in[6];
    const float* W3   = (const float*)d_in[7];
    const float* b3   = (const float*)d_in[8];
    const float* lpW1 = (const float*)d_in[9];
    const float* lpb1 = (const float*)d_in[10];
    const float* lpW2 = (const float*)d_in[11];
    const float* lpb2 = (const float*)d_in[12];
    float* out = (float*)d_out;

    int N  = in_sizes[0] / FIN;
    int E  = in_sizes[1] / 2;
    int EL = in_sizes[2] / 2;

    const int T = 256;
    int nBlkN = (N + T - 1) / T;
    int nBlkE = (E + T - 1) / T;
    int scanBlocks = (N + 1023) / 1024;
    int gemmBlocks = (N + 127) / 128;

    int warps64 = (N + 3) / 4;                      // H=64: 4 nodes/warp
    int agg64Blocks = (warps64 * 32 + T - 1) / T;
    int warps32 = (N + 7) / 8;                      // H=32: 8 nodes/warp
    int agg32Blocks = (warps32 * 32 + T - 1) / T;

    float* zout = out + EL;

    // fork/join plumbing: built-in second stream (no creation), untimed events
    cudaStream_t main_s = 0;
    cudaStream_t side_s = cudaStreamPerThread;
    cudaEvent_t ev_fork, ev_join;
    cudaEventCreateWithFlags(&ev_fork, cudaEventDisableTiming);
    cudaEventCreateWithFlags(&ev_join, cudaEventDisableTiming);

    // CSR build prefix (main stream)
    k_detect<<<1, 256, 0, main_s>>>((const int*)ei);
    k_zero_cnt<<<nBlkN, T, 0, main_s>>>(N);
    k_count<<<nBlkE, T, 0, main_s>>>(ei, E, N);
    k_scan1<<<scanBlocks, 1024, 0, main_s>>>(N);   // dinv ready after this

    // fork: GEMM1 (needs x, W1, dinv) runs parallel to scan2/scan3/fill
    cudaEventRecord(ev_fork, main_s);
    cudaStreamWaitEvent(side_s, ev_fork, 0);
    k_gemm<FIN, HID, false, false, OM_H16S><<<gemmBlocks, 128, 0, side_s>>>(x, nullptr, W1, N);
    cudaEventRecord(ev_join, side_s);

    // CSR build suffix (main stream)
    k_scan2<<<1, 128, 0, main_s>>>(N);
    k_scan3<<<nBlkN, T, 0, main_s>>>(N);
    k_fill<<<nBlkE, T, 0, main_s>>>(ei, E, N);

    // join: aggregate needs both g_hh (side) and CSR (main)
    cudaStreamWaitEvent(main_s, ev_join, 0);

    // encoder (main stream from here on)
    k_agg16<HID, false><<<agg64Blocks, T, 0, main_s>>>(N, nullptr, nullptr);

    k_gemm<HID, HID, true, true, OM_H16S><<<gemmBlocks, 128, 0, main_s>>>(nullptr, b1, W2, N);
    k_agg16<HID, false><<<agg64Blocks, T, 0, main_s>>>(N, nullptr, nullptr);

    k_gemm<HID, OUTD, true, true, OM_H16S><<<gemmBlocks, 64, 0, main_s>>>(nullptr, b2, W3, N);
    k_agg16<OUTD, true><<<agg32Blocks, T, 0, main_s>>>(N, b3, zout);

    // fused decoder precompute: [u|v] = z @ [lpW1_top | lpW1_bot] (fp16 out)
    k_gemm<OUTD, 128, false, false, OM_SPLIT16><<<gemmBlocks, 256, 0, main_s>>>(zout, nullptr, lpW1, N);

    // decoder-lite: 4 edges/warp, fp16 gathers
    int warpsD = (EL + 3) / 4;
    int decBlocks = (warpsD * 32 + T - 1) / T;
    k_decode_lite<<<decBlocks, T, 0, main_s>>>(eli, lpb1, lpW2, lpb2, out, EL, N);
}

// round 15
// speedup vs baseline: 1.0592x; 1.0226x over previous
#include <cuda_runtime.h>
#include <cuda_fp16.h>
#include <cstdint>

#define N_MAX   100000
#define E_MAX   3200000
#define FIN     128
#define HID     64
#define OUTD    32
#define SCAN_B  ((N_MAX + 1023) / 1024)   // 98

__device__ __align__(16) __half g_hh [(size_t)N_MAX * HID];   // fp16 scaled hs / u
__device__ __align__(16) __half g_vv [(size_t)N_MAX * HID];   // fp16 v
__device__ __align__(16) __half g_ag [(size_t)N_MAX * HID];   // fp16 inter-layer agg
__device__ int   g_cnt   [N_MAX];
__device__ float g_dinv  [N_MAX];
__device__ int   g_rowptr[N_MAX + 1];
__device__ int   g_cursor[N_MAX];
__device__ int   g_bsum  [SCAN_B];
__device__ int   g_csr   [E_MAX];                             // src only
__device__ int   g_is64;

// k_gemm output modes
#define OM_H16S    0   // fp16, scaled by dinv[node], -> g_hh
#define OM_SPLIT16 1   // fp16 u -> g_hh, v -> g_vv (M=128, W = [lpW1_top|lpW1_bot])

__device__ __forceinline__ unsigned long long fma2(unsigned long long a,
                                                   unsigned long long b,
                                                   unsigned long long c) {
    unsigned long long d;
    asm("fma.rn.f32x2 %0, %1, %2, %3;" : "=l"(d) : "l"(a), "l"(b), "l"(c));
    return d;
}
__device__ __forceinline__ unsigned long long pack2(float lo, float hi) {
    unsigned long long r;
    asm("mov.b64 %0, {%1, %2};" : "=l"(r) : "f"(lo), "f"(hi));
    return r;
}
__device__ __forceinline__ float2 unpack2(unsigned long long v) {
    float2 r;
    asm("mov.b64 {%0, %1}, %2;" : "=f"(r.x), "=f"(r.y) : "l"(v));
    return r;
}
__device__ __forceinline__ void h16x8_to_f32(uint4 r, float* v) {
    const __half2* h = (const __half2*)&r;
    float2 f0 = __half22float2(h[0]);
    float2 f1 = __half22float2(h[1]);
    float2 f2 = __half22float2(h[2]);
    float2 f3 = __half22float2(h[3]);
    v[0] = f0.x; v[1] = f0.y; v[2] = f1.x; v[3] = f1.y;
    v[4] = f2.x; v[5] = f2.y; v[6] = f3.x; v[7] = f3.y;
}

__device__ __forceinline__ int load_idx(const void* buf, size_t e, int is64, int n) {
    int v;
    if (is64) v = (int)((const long long*)buf)[e];
    else      v = ((const int*)buf)[e];
    if ((unsigned)v >= (unsigned)n) v = 0;
    return v;
}

// ---- detect dtype (block 0) + zero cnt (all blocks) ----
__global__ void k_detect_zero(const int* __restrict__ raw, int n) {
    int i = blockIdx.x * blockDim.x + threadIdx.x;
    if (i < n) g_cnt[i] = 0;
    if (blockIdx.x == 0) {
        __shared__ int s_nz;
        if (threadIdx.x == 0) s_nz = 0;
        __syncthreads();
        int nz = 0;
        for (int k = threadIdx.x; k < 512; k += blockDim.x)
            nz |= raw[2 * k + 1];
        if (nz) atomicOr(&s_nz, 1);
        __syncthreads();
        if (threadIdx.x == 0) g_is64 = (s_nz == 0) ? 1 : 0;
    }
}

__global__ void k_count(const void* __restrict__ ei, int nE, int n) {
    int e = blockIdx.x * blockDim.x + threadIdx.x;
    if (e >= nE) return;
    int is64 = g_is64;
    int c = load_idx(ei, (size_t)nE + e, is64, n);
    atomicAdd(&g_cnt[c], 1);
}

// ---- phase 1: per-block local scan + dinv ----
__global__ void k_scan1(int n) {
    __shared__ int sh[1024];
    int tid = threadIdx.x;
    int i = blockIdx.x * 1024 + tid;
    int v = (i < n) ? g_cnt[i] : 0;
    if (i < n) g_dinv[i] = rsqrtf((float)v + 1.0f);
    sh[tid] = v;
    __syncthreads();
    #pragma unroll
    for (int off = 1; off < 1024; off <<= 1) {
        int t = (tid >= off) ? sh[tid - off] : 0;
        __syncthreads();
        sh[tid] += t;
        __syncthreads();
    }
    if (i < n) g_rowptr[i] = sh[tid] - v;
    if (tid == 1023) g_bsum[blockIdx.x] = sh[1023];
}

// ---- phase 2 (merged): add block offsets + init cursor; each 256-thread block
// recomputes its chunk's prefix from g_bsum (<=98 ints). Last block sets rowptr[n].
__global__ void k_scan3(int n) {
    __shared__ int s_pre, s_tot;
    int tid = threadIdx.x;
    int i = blockIdx.x * 256 + tid;
    int c = blockIdx.x >> 2;                 // 1024-chunk index (256*4)
    int nchunks = (n + 1023) >> 10;

    int v    = (tid < nchunks && tid < SCAN_B) ? g_bsum[tid] : 0;
    int vpre = (tid < c) ? v : 0;
    #pragma unroll
    for (int off = 16; off; off >>= 1) {
        vpre += __shfl_down_sync(0xffffffffu, vpre, off);
        v    += __shfl_down_sync(0xffffffffu, v,    off);
    }
    if (tid == 0) { s_pre = 0; s_tot = 0; }
    __syncthreads();
    if ((tid & 31) == 0) { atomicAdd(&s_pre, vpre); atomicAdd(&s_tot, v); }
    __syncthreads();

    if (i < n) {
        int r = g_rowptr[i] + s_pre;
        g_rowptr[i] = r;
        g_cursor[i] = r;
    }
    if (blockIdx.x == gridDim.x - 1 && tid == 0) g_rowptr[n] = s_tot;
}

__global__ void k_fill(const void* __restrict__ ei, int nE, int n) {
    int e = blockIdx.x * blockDim.x + threadIdx.x;
    if (e >= nE) return;
    int is64 = g_is64;
    int r = load_idx(ei, (size_t)e, is64, n);
    int c = load_idx(ei, (size_t)nE + e, is64, n);
    int pos = atomicAdd(&g_cursor[c], 1);
    if (pos >= 0 && pos < E_MAX) g_csr[pos] = r;
}

// ---------------- register-tiled GEMM (f32x2) ----------------
// SRC_AGG16: stage input from fp16 g_ag; else from Xext (fp32).
template<int K, int M, bool RELU, bool SRC_AGG16, int OMODE>
__global__ void k_gemm(const float* __restrict__ Xext,
                       const float* __restrict__ Bk,
                       const float* __restrict__ W, int n) {
    constexpr int KC = (K < 64) ? K : 64;
    constexpr int JG = M / 8;
    constexpr int THREADS = 16 * JG;
    constexpr int XS = 132;
    __shared__ float sW[KC * M];
    __shared__ float sXT[KC][XS];

    int tid = threadIdx.x;
    int jg  = tid & (JG - 1);
    int ng  = tid / JG;
    int n0  = blockIdx.x * 128;

    unsigned long long acc2[8][4];
    #pragma unroll
    for (int e = 0; e < 8; e++)
        #pragma unroll
        for (int jj = 0; jj < 4; jj++) acc2[e][jj] = 0ull;

    for (int kc = 0; kc < K; kc += KC) {
        if (OMODE == OM_SPLIT16) {
            for (int i = tid; i < KC * M; i += THREADS) {
                int k = i / M, j = i % M;
                sW[i] = (j < 64) ? W[(size_t)(kc + k) * 64 + j]
                                 : W[(size_t)(kc + k + K) * 64 + (j - 64)];
            }
        } else {
            for (int i = tid; i < KC * M; i += THREADS)
                sW[i] = W[(size_t)kc * M + i];
        }
        for (int nl = tid; nl < 128; nl += THREADS) {
            int node = n0 + nl;
            if (SRC_AGG16) {
                #pragma unroll
                for (int q = 0; q < KC / 8; q++) {
                    float v[8] = {0,0,0,0,0,0,0,0};
                    if (node < n) {
                        uint4 r = *(const uint4*)(g_ag + (size_t)node * K + kc + q * 8);
                        h16x8_to_f32(r, v);
                        if (RELU) {
                            #pragma unroll
                            for (int i = 0; i < 8; i++)
                                v[i] = fmaxf(v[i] + Bk[kc + q * 8 + i], 0.f);
                        }
                    }
                    #pragma unroll
                    for (int i = 0; i < 8; i++) sXT[q * 8 + i][nl] = v[i];
                }
            } else {
                #pragma unroll
                for (int q = 0; q < KC / 4; q++) {
                    float4 v = make_float4(0.f, 0.f, 0.f, 0.f);
                    if (node < n) {
                        v = *(const float4*)(Xext + (size_t)node * K + kc + q * 4);
                        if (RELU) {
                            v.x = fmaxf(v.x + Bk[kc + q * 4 + 0], 0.f);
                            v.y = fmaxf(v.y + Bk[kc + q * 4 + 1], 0.f);
                            v.z = fmaxf(v.z + Bk[kc + q * 4 + 2], 0.f);
                            v.w = fmaxf(v.w + Bk[kc + q * 4 + 3], 0.f);
                        }
                    }
                    sXT[q * 4 + 0][nl] = v.x;
                    sXT[q * 4 + 1][nl] = v.y;
                    sXT[q * 4 + 2][nl] = v.z;
                    sXT[q * 4 + 3][nl] = v.w;
                }
            }
        }
        __syncthreads();

        #pragma unroll 4
        for (int k = 0; k < KC; k++) {
            float4 a0 = *(const float4*)&sXT[k][ng * 8];
            float4 a1 = *(const float4*)&sXT[k][ng * 8 + 4];
            const float2* wr = (const float2*)&sW[k * M + jg * 8];
            unsigned long long w0 = pack2(wr[0].x, wr[0].y);
            unsigned long long w1 = pack2(wr[1].x, wr[1].y);
            unsigned long long w2 = pack2(wr[2].x, wr[2].y);
            unsigned long long w3 = pack2(wr[3].x, wr[3].y);
            float av[8] = {a0.x, a0.y, a0.z, a0.w, a1.x, a1.y, a1.z, a1.w};
            #pragma unroll
            for (int e = 0; e < 8; e++) {
                unsigned long long x2 = pack2(av[e], av[e]);
                acc2[e][0] = fma2(x2, w0, acc2[e][0]);
                acc2[e][1] = fma2(x2, w1, acc2[e][1]);
                acc2[e][2] = fma2(x2, w2, acc2[e][2]);
                acc2[e][3] = fma2(x2, w3, acc2[e][3]);
            }
        }
        __syncthreads();
    }

    #pragma unroll
    for (int e = 0; e < 8; e++) {
        int node = n0 + ng * 8 + e;
        if (node >= n) continue;
        uint4 pkt;
        __half2* ph = (__half2*)&pkt;
        if (OMODE == OM_H16S) {
            float dv = g_dinv[node];
            #pragma unroll
            for (int jj = 0; jj < 4; jj++) {
                float2 f = unpack2(acc2[e][jj]);
                ph[jj] = __floats2half2_rn(f.x * dv, f.y * dv);
            }
            *(uint4*)(g_hh + (size_t)node * M + jg * 8) = pkt;
        } else {   // OM_SPLIT16
            #pragma unroll
            for (int jj = 0; jj < 4; jj++) {
                float2 f = unpack2(acc2[e][jj]);
                ph[jj] = __floats2half2_rn(f.x, f.y);
            }
            __half* dst = (jg < 8) ? (g_hh + (size_t)node * 64 + jg * 8)
                                   : (g_vv + (size_t)node * 64 + (jg - 8) * 8);
            *(uint4*)dst = pkt;
        }
    }
}

// ---------------- aggregation over scaled fp16 hs ----------------
// acc = hs[c] + sum_e hs[src(e)];  result = dinv[c]*acc
// FINAL: +bias, fp32 -> zout; else fp16 -> g_ag.
template<int H, bool FINAL>
__global__ void k_agg16(int n, const float* __restrict__ bias,
                        float* __restrict__ zout) {
    constexpr int LPN = H / 8;
    constexpr int NPW = 32 / LPN;
    int gw   = (blockIdx.x * blockDim.x + threadIdx.x) >> 5;
    int lane = threadIdx.x & 31;
    int node = gw * NPW + lane / LPN;
    int fl   = lane % LPN;
    if (node >= n) return;

    float acc[8], v0[8], v1[8];
    uint4 rs = *(const uint4*)(g_hh + (size_t)node * H + fl * 8);
    h16x8_to_f32(rs, acc);

    int beg = g_rowptr[node];
    int end = g_rowptr[node + 1];
    int e = beg;
    for (; e + 1 < end; e += 2) {
        int s0 = g_csr[e];
        int s1 = g_csr[e + 1];
        uint4 r0 = *(const uint4*)(g_hh + (size_t)s0 * H + fl * 8);
        uint4 r1 = *(const uint4*)(g_hh + (size_t)s1 * H + fl * 8);
        h16x8_to_f32(r0, v0);
        h16x8_to_f32(r1, v1);
        #pragma unroll
        for (int i = 0; i < 8; i++) acc[i] += v0[i];
        #pragma unroll
        for (int i = 0; i < 8; i++) acc[i] += v1[i];
    }
    if (e < end) {
        int s0 = g_csr[e];
        uint4 r0 = *(const uint4*)(g_hh + (size_t)s0 * H + fl * 8);
        h16x8_to_f32(r0, v0);
        #pragma unroll
        for (int i = 0; i < 8; i++) acc[i] += v0[i];
    }

    float dv = g_dinv[node];
    if (FINAL) {
        float* dst = zout + (size_t)node * H + fl * 8;
        float4 b0 = *(const float4*)(bias + fl * 8);
        float4 b1 = *(const float4*)(bias + fl * 8 + 4);
        *(float4*)(dst)     = make_float4(acc[0] * dv + b0.x, acc[1] * dv + b0.y,
                                          acc[2] * dv + b0.z, acc[3] * dv + b0.w);
        *(float4*)(dst + 4) = make_float4(acc[4] * dv + b1.x, acc[5] * dv + b1.y,
                                          acc[6] * dv + b1.z, acc[7] * dv + b1.w);
    } else {
        uint4 pkt;
        __half2* ph = (__half2*)&pkt;
        #pragma unroll
        for (int jj = 0; jj < 4; jj++)
            ph[jj] = __floats2half2_rn(acc[jj * 2] * dv, acc[jj * 2 + 1] * dv);
        *(uint4*)(g_ag + (size_t)node * H + fl * 8) = pkt;
    }
}

// ---------------- decoder-lite (fp16 u/v) ----------------
__global__ void k_decode_lite(const void* __restrict__ eli,
                              const float* __restrict__ b1,
                              const float* __restrict__ w2,
                              const float* __restrict__ b2,
                              float* __restrict__ out, int nE, int nNodes) {
    int gw   = (blockIdx.x * blockDim.x + threadIdx.x) >> 5;
    int lane = threadIdx.x & 31;
    int sub  = lane >> 3;
    int fl   = lane & 7;

    int e = gw * 4 + sub;
    if (e >= nE) return;

    int is64 = g_is64;
    int src = load_idx(eli, (size_t)e, is64, nNodes);
    int dst = load_idx(eli, (size_t)nE + e, is64, nNodes);

    uint4 ru = *(const uint4*)(g_hh + (size_t)src * HID + fl * 8);
    uint4 rv = *(const uint4*)(g_vv + (size_t)dst * HID + fl * 8);
    float uu[8], vv[8];
    h16x8_to_f32(ru, uu);
    h16x8_to_f32(rv, vv);
    float4 b0 = *(const float4*)(b1 + fl * 8);
    float4 b1v = *(const float4*)(b1 + fl * 8 + 4);
    float4 w0 = *(const float4*)(w2 + fl * 8);
    float4 w1 = *(const float4*)(w2 + fl * 8 + 4);
    float bb[8] = {b0.x, b0.y, b0.z, b0.w, b1v.x, b1v.y, b1v.z, b1v.w};
    float ww[8] = {w0.x, w0.y, w0.z, w0.w, w1.x, w1.y, w1.z, w1.w};

    float p = 0.f;
    #pragma unroll
    for (int i = 0; i < 8; i++)
        p += fmaxf(uu[i] + vv[i] + bb[i], 0.f) * ww[i];

    p += __shfl_down_sync(0xffffffffu, p, 4, 8);
    p += __shfl_down_sync(0xffffffffu, p, 2, 8);
    p += __shfl_down_sync(0xffffffffu, p, 1, 8);

    if (fl == 0) out[e] = p + b2[0];
}

extern "C" void kernel_launch(void* const* d_in, const int* in_sizes, int n_in,
                              void* d_out, int out_size) {
    const float* x    = (const float*)d_in[0];
    const void*  ei   = d_in[1];
    const void*  eli  = d_in[2];
    const float* W1   = (const float*)d_in[3];
    const float* b1   = (const float*)d_in[4];
    const float* W2   = (const float*)d_in[5];
    const float* b2   = (const float*)d_in[6];
    const float* W3   = (const float*)d_in[7];
    const float* b3   = (const float*)d_in[8];
    const float* lpW1 = (const float*)d_in[9];
    const float* lpb1 = (const float*)d_in[10];
    const float* lpW2 = (const float*)d_in[11];
    const float* lpb2 = (const float*)d_in[12];
    float* out = (float*)d_out;

    int N  = in_sizes[0] / FIN;
    int E  = in_sizes[1] / 2;
    int EL = in_sizes[2] / 2;

    const int T = 256;
    int nBlkN = (N + T - 1) / T;
    int nBlkE = (E + T - 1) / T;
    int scanBlocks = (N + 1023) / 1024;
    int gemmBlocks = (N + 127) / 128;

    int warps64 = (N + 3) / 4;                      // H=64: 4 nodes/warp
    int agg64Blocks = (warps64 * 32 + T - 1) / T;
    int warps32 = (N + 7) / 8;                      // H=32: 8 nodes/warp
    int agg32Blocks = (warps32 * 32 + T - 1) / T;

    float* zout = out + EL;

    // CSR build (12.8MB int CSR; dinv fused into scan1; boff fused into scan3)
    k_detect_zero<<<nBlkN, T>>>((const int*)ei, N);
    k_count<<<nBlkE, T>>>(ei, E, N);
    k_scan1<<<scanBlocks, 1024>>>(N);
    k_scan3<<<nBlkN, T>>>(N);
    k_fill<<<nBlkE, T>>>(ei, E, N);

    // encoder: layers emit dinv-scaled fp16 hs; aggregates accumulate fp32,
    // store inter-layer result fp16 (g_ag)
    k_gemm<FIN, HID, false, false, OM_H16S><<<gemmBlocks, 128>>>(x, nullptr, W1, N);
    k_agg16<HID, false><<<agg64Blocks, T>>>(N, nullptr, nullptr);

    k_gemm<HID, HID, true, true, OM_H16S><<<gemmBlocks, 128>>>(nullptr, b1, W2, N);
    k_agg16<HID, false><<<agg64Blocks, T>>>(N, nullptr, nullptr);

    k_gemm<HID, OUTD, true, true, OM_H16S><<<gemmBlocks, 64>>>(nullptr, b2, W3, N);
    k_agg16<OUTD, true><<<agg32Blocks, T>>>(N, b3, zout);

    // fused decoder precompute: [u|v] = z @ [lpW1_top | lpW1_bot] (fp16 out)
    k_gemm<OUTD, 128, false, false, OM_SPLIT16><<<gemmBlocks, 256>>>(zout, nullptr, lpW1, N);

    // decoder-lite: 4 edges/warp, fp16 gathers
    int warpsD = (EL + 3) / 4;
    int decBlocks = (warpsD * 32 + T - 1) / T;
    k_decode_lite<<<decBlocks, T>>>(eli, lpb1, lpW2, lpb2, out, EL, N);
}